// round 12
// baseline (speedup 1.0000x reference)
#include <cuda_runtime.h>
#include <cuda_bf16.h>
#include <math.h>
#include <stdint.h>

// ---------------- problem constants ----------------
#define B_ROWS 65536
#define V_DIM  3
#define D_DIM  64
#define K_CB   1024
#define S_ST   4
#define H_DIM  1024
#define L_NUM  5
#define F_NUM  25
#define IN_DIM 102     // C*(2F+1)
#define IN_PAD 128     // padded K for layer 0

// ---------------- GEMM tiling (mma.sync path, base sm_103 ISA) ------------
// CTA 128x256, 8 warps in 2(m) x 4(n), warp tile 64x64. BK=32, 3 stages.
#define BM 128
#define BN 256
#define BK 32
#define ASTRIDE 40                       // bf16 elems per smem row (80 B, conflict-free ldmatrix)
#define A_TILE_SMEM (BM * ASTRIDE * 2)   // 10240 B  (128 rows x 80 B)
#define B_TILE_SMEM (BN * ASTRIDE * 2)   // 20480 B  (256 rows x 80 B)
#define STAGE_SMEM (2 * A_TILE_SMEM + 2 * B_TILE_SMEM)   // 61440 B: Ahi, Alo, Bhi, Blo
#define NSTAGE 3
#define SMEM_GEMM_TOTAL (NSTAGE * STAGE_SMEM + 1024 + 64)    // + bias(256 f32)

// ---------------- persistent scratch (no cudaMalloc allowed) ---------------
__device__ __nv_bfloat16 g_pe_hi[(size_t)B_ROWS * IN_PAD];
__device__ __nv_bfloat16 g_pe_lo[(size_t)B_ROWS * IN_PAD];
__device__ __nv_bfloat16 g_ha_hi[(size_t)B_ROWS * H_DIM];
__device__ __nv_bfloat16 g_ha_lo[(size_t)B_ROWS * H_DIM];
__device__ __nv_bfloat16 g_hb_hi[(size_t)B_ROWS * H_DIM];
__device__ __nv_bfloat16 g_hb_lo[(size_t)B_ROWS * H_DIM];
__device__ __nv_bfloat16 g_w0t_hi[(size_t)H_DIM * IN_PAD];
__device__ __nv_bfloat16 g_w0t_lo[(size_t)H_DIM * IN_PAD];
__device__ __nv_bfloat16 g_wt_hi[(size_t)H_DIM * H_DIM];
__device__ __nv_bfloat16 g_wt_lo[(size_t)H_DIM * H_DIM];
__device__ float g_bias[L_NUM * H_DIM];

// ---------------- PTX helpers (all base-ISA, no 'a' features) --------------
__device__ __forceinline__ uint32_t smem_to_u32(const void* p) {
    uint32_t a;
    asm("{ .reg .u64 t; cvta.to.shared.u64 t, %1; cvt.u32.u64 %0, t; }" : "=r"(a) : "l"(p));
    return a;
}
#define CP_ASYNC16(saddr, gptr) \
    asm volatile("cp.async.cg.shared.global [%0], [%1], 16;" :: "r"(saddr), "l"(gptr))
#define CP_COMMIT() asm volatile("cp.async.commit_group;" ::: "memory")
#define CP_WAIT(n)  asm volatile("cp.async.wait_group %0;" :: "n"(n) : "memory")
#define LDSM4(r0, r1, r2, r3, addr) \
    asm volatile("ldmatrix.sync.aligned.m8n8.x4.shared.b16 {%0,%1,%2,%3}, [%4];" \
        : "=r"(r0), "=r"(r1), "=r"(r2), "=r"(r3) : "r"(addr))
#define MMA16816(d, a0, a1, a2, a3, b0, b1) \
    asm volatile("mma.sync.aligned.m16n8k16.row.col.f32.bf16.bf16.f32 " \
        "{%0,%1,%2,%3}, {%4,%5,%6,%7}, {%8,%9}, {%0,%1,%2,%3};" \
        : "+f"((d)[0]), "+f"((d)[1]), "+f"((d)[2]), "+f"((d)[3]) \
        : "r"(a0), "r"(a1), "r"(a2), "r"(a3), "r"(b0), "r"(b1))

__device__ __forceinline__ void split_bf16(float v, __nv_bfloat16& hi, __nv_bfloat16& lo) {
    hi = __float2bfloat16(v);
    lo = __float2bfloat16(v - __bfloat162float(hi));
}

// ---------------- float-float (df) arithmetic, fast-math-immune ------------
struct df2 { float h, l; };

__device__ __forceinline__ df2 df_norm(float p, float e) {
    float hi = __fadd_rn(p, e);
    float lo = __fsub_rn(e, __fsub_rn(hi, p));
    df2 r; r.h = hi; r.l = lo; return r;
}
__device__ __forceinline__ df2 df_mul(df2 a, df2 b) {
    float p = __fmul_rn(a.h, b.h);
    float e = __fmaf_rn(a.h, b.h, -p);
    e = __fmaf_rn(a.h, b.l, e);
    e = __fmaf_rn(a.l, b.h, e);
    return df_norm(p, e);
}
__device__ __forceinline__ df2 df_one_minus2(df2 t) {
    float b = __fmul_rn(-2.0f, t.h);          // exact
    float s = __fadd_rn(1.0f, b);
    float z = __fsub_rn(s, 1.0f);
    float err = __fadd_rn(__fsub_rn(1.0f, __fsub_rn(s, z)), __fsub_rn(b, z));
    err = __fmaf_rn(-2.0f, t.l, err);
    return df_norm(s, err);
}

// ============================================================================
// Setup kernel: VQ argmin, commit loss, z_q_sum, fused biases (verified R3)
// ============================================================================
__global__ void setup_kernel(const float* __restrict__ latents,
                             const int*   __restrict__ latent_idx,
                             const float* __restrict__ codebooks,
                             const float* __restrict__ mod_W,
                             const float* __restrict__ mod_b,
                             const float* __restrict__ dec_b0,
                             const float* __restrict__ dec_bh,
                             float* __restrict__ out, int out_size)
{
    __shared__ float s_img[S_ST * D_DIM];
    __shared__ float s_zsum[D_DIM];
    __shared__ float s_zz[S_ST];
    __shared__ float s_dist[K_CB];
    __shared__ int   s_didx[K_CB];
    __shared__ int   s_widx[S_ST];
    __shared__ float s_loss[S_ST];
    __shared__ float s_tmp[D_DIM];

    int tid = threadIdx.x;
    const float* img = latents + (size_t)latent_idx[0] * S_ST * D_DIM;
    if (tid < S_ST * D_DIM) s_img[tid] = img[tid];
    __syncthreads();
    if (tid < D_DIM)
        s_zsum[tid] = s_img[tid] + s_img[D_DIM + tid] + s_img[2*D_DIM + tid] + s_img[3*D_DIM + tid];
    if (tid < S_ST) {
        float zz = 0.f;
        for (int d = 0; d < D_DIM; d++) { float v = s_img[tid*D_DIM + d]; zz += v * v; }
        s_zz[tid] = zz;
    }
    __syncthreads();
    for (int s = 0; s < S_ST; s++) {
        const float* z = &s_img[s * D_DIM];
        const float* e = codebooks + ((size_t)s * K_CB + tid) * D_DIM;
        float dot = 0.f, ee = 0.f;
        #pragma unroll 8
        for (int d = 0; d < D_DIM; d++) { float ev = e[d]; dot += z[d] * ev; ee += ev * ev; }
        s_dist[tid] = s_zz[s] - 2.f * dot + ee;
        s_didx[tid] = tid;
        __syncthreads();
        for (int off = K_CB / 2; off > 0; off >>= 1) {
            if (tid < off) {
                float d1 = s_dist[tid], d2 = s_dist[tid + off];
                int i1 = s_didx[tid], i2 = s_didx[tid + off];
                if (d2 < d1 || (d2 == d1 && i2 < i1)) { s_dist[tid] = d2; s_didx[tid] = i2; }
            }
            __syncthreads();
        }
        if (tid == 0) s_widx[s] = s_didx[0];
        __syncthreads();
        if (tid < D_DIM) {
            float diff = codebooks[((size_t)s * K_CB + s_widx[s]) * D_DIM + tid] - z[tid];
            s_tmp[tid] = diff * diff;
        }
        __syncthreads();
        if (tid == 0) {
            float ssum = 0.f;
            for (int d = 0; d < D_DIM; d++) ssum += s_tmp[d];
            s_loss[s] = 0.25f * (ssum / (float)D_DIM);
        }
        __syncthreads();
    }
    {
        int n = tid;
        for (int l = 0; l < L_NUM; l++) {
            float acc = mod_b[l * H_DIM + n];
            const float* Wl = mod_W + (size_t)l * D_DIM * H_DIM + n;
            #pragma unroll 8
            for (int d = 0; d < D_DIM; d++) acc += s_zsum[d] * Wl[(size_t)d * H_DIM];
            acc += (l == 0) ? dec_b0[n] : dec_bh[(l - 1) * H_DIM + n];
            g_bias[l * H_DIM + n] = acc;
        }
    }
    if (tid == 0 && out_size >= B_ROWS * V_DIM + S_ST + 1) {
        float tl = 0.f;
        for (int s = 0; s < S_ST; s++) { out[B_ROWS * V_DIM + s] = (float)s_widx[s]; tl += s_loss[s]; }
        out[B_ROWS * V_DIM + S_ST] = tl;
    }
}

// ============================================================================
// PE kernel: one thread per point; one double sincos seed + df double-angle.
// ============================================================================
__global__ void pe_kernel(const float* __restrict__ coords)
{
    int b = blockIdx.x * blockDim.x + threadIdx.x;
    if (b >= B_ROWS) return;
    float x = coords[b * 2 + 0];
    float y = coords[b * 2 + 1];
    const float PIF = 3.14159265358979323846f;   // fl(pi)

    float a0x = __fmul_rn(x, PIF);
    float a0y = __fmul_rn(y, PIF);
    double sdx, cdx, sdy, cdy;
    sincos((double)a0x, &sdx, &cdx);
    sincos((double)a0y, &sdy, &cdy);

    df2 sx, cx, sy, cy;
    sx.h = (float)sdx; sx.l = (float)(sdx - (double)sx.h);
    cx.h = (float)cdx; cx.l = (float)(cdx - (double)cx.h);
    sy.h = (float)sdy; sy.l = (float)(sdy - (double)sy.h);
    cy.h = (float)cdy; cy.l = (float)(cdy - (double)cy.h);

    size_t base = (size_t)b * IN_PAD;
    uint32_t* rh = (uint32_t*)(g_pe_hi + base);
    uint32_t* rl = (uint32_t*)(g_pe_lo + base);

    {
        __nv_bfloat16 xh, xl, yh, yl;
        split_bf16(x, xh, xl); split_bf16(y, yh, yl);
        rh[0] = (uint32_t)__bfloat16_as_ushort(xh) | ((uint32_t)__bfloat16_as_ushort(yh) << 16);
        rl[0] = (uint32_t)__bfloat16_as_ushort(xl) | ((uint32_t)__bfloat16_as_ushort(yl) << 16);
    }

    #pragma unroll 1
    for (int f = 0; f < F_NUM; f++) {
        float svx = __fadd_rn(sx.h, sx.l), cvx = __fadd_rn(cx.h, cx.l);
        float svy = __fadd_rn(sy.h, sy.l), cvy = __fadd_rn(cy.h, cy.l);
        __nv_bfloat16 h0, l0, h1, l1;
        split_bf16(svx, h0, l0); split_bf16(svy, h1, l1);
        rh[1 + 2*f] = (uint32_t)__bfloat16_as_ushort(h0) | ((uint32_t)__bfloat16_as_ushort(h1) << 16);
        rl[1 + 2*f] = (uint32_t)__bfloat16_as_ushort(l0) | ((uint32_t)__bfloat16_as_ushort(l1) << 16);
        split_bf16(cvx, h0, l0); split_bf16(cvy, h1, l1);
        rh[2 + 2*f] = (uint32_t)__bfloat16_as_ushort(h0) | ((uint32_t)__bfloat16_as_ushort(h1) << 16);
        rl[2 + 2*f] = (uint32_t)__bfloat16_as_ushort(l0) | ((uint32_t)__bfloat16_as_ushort(l1) << 16);
        if (f < F_NUM - 1) {
            df2 s2 = df_mul(sx, cx); s2.h = __fmul_rn(s2.h, 2.f); s2.l = __fmul_rn(s2.l, 2.f);
            df2 ss = df_mul(sx, sx);
            cx = df_one_minus2(ss); sx = s2;
            s2 = df_mul(sy, cy); s2.h = __fmul_rn(s2.h, 2.f); s2.l = __fmul_rn(s2.l, 2.f);
            ss = df_mul(sy, sy);
            cy = df_one_minus2(ss); sy = s2;
        }
    }
    #pragma unroll
    for (int i = 51; i < 64; i++) { rh[i] = 0u; rl[i] = 0u; }
}

// ============================================================================
// Weight transpose + bf16 split:  W[K,1024] fp32  ->  Wt_hi/lo[1024, Kpad] bf16
// ============================================================================
__global__ void wsplit_kernel(const float* __restrict__ W, int Keff, int Kpad,
                              __nv_bfloat16* __restrict__ Th, __nv_bfloat16* __restrict__ Tl)
{
    __shared__ float t[32][33];
    int n0 = blockIdx.x * 32, k0 = blockIdx.y * 32;
    int tx = threadIdx.x, ty = threadIdx.y;    // (32, 8)
    #pragma unroll
    for (int r = 0; r < 4; r++) {
        int k = k0 + ty + r * 8;
        t[ty + r * 8][tx] = (k < Keff) ? W[(size_t)k * H_DIM + n0 + tx] : 0.f;
    }
    __syncthreads();
    #pragma unroll
    for (int r = 0; r < 4; r++) {
        int n = n0 + ty + r * 8;
        int k = k0 + tx;
        float v = t[tx][ty + r * 8];
        __nv_bfloat16 hi, lo; split_bf16(v, hi, lo);
        Th[(size_t)n * Kpad + k] = hi;
        Tl[(size_t)n * Kpad + k] = lo;
    }
}

// ============================================================================
// mma.sync split-bf16 GEMM:  C = relu(A @ Wt^T + bias), emitted as bf16 hi/lo
// CTA 128x256, 8 warps 2x4, warp tile 64x64, BK=32, 3-stage cp.async pipeline.
// TERM-MAJOR MMA ordering: dependent MMAs on the same accumulator are
// separated by 8 independent issues -> HMMA RAW latency fully hidden.
// ============================================================================
template<int ROWS>
__device__ __forceinline__ void cpa_tile(uint32_t sdst, const __nv_bfloat16* __restrict__ src,
                                         int r0, int ld, int kt, int tid)
{
    #pragma unroll
    for (int it = 0; it < ROWS / 64; it++) {
        int idx = it * 256 + tid;
        int row = idx >> 2, ch = idx & 3;
        uint32_t s = sdst + (uint32_t)(row * 80 + ch * 16);
        const __nv_bfloat16* g = src + (size_t)(r0 + row) * ld + kt + ch * 8;
        CP_ASYNC16(s, (unsigned long long)__cvta_generic_to_global(g));
    }
}
__device__ __forceinline__ void cpa_stage(uint32_t dst,
        const __nv_bfloat16* Ahi, const __nv_bfloat16* Alo, int m0, int lda,
        const __nv_bfloat16* Bhi, const __nv_bfloat16* Blo, int n0, int ldb,
        int kt, int tid)
{
    cpa_tile<BM>(dst,                                   Ahi, m0, lda, kt, tid);
    cpa_tile<BM>(dst + A_TILE_SMEM,                     Alo, m0, lda, kt, tid);
    cpa_tile<BN>(dst + 2 * A_TILE_SMEM,                 Bhi, n0, ldb, kt, tid);
    cpa_tile<BN>(dst + 2 * A_TILE_SMEM + B_TILE_SMEM,   Blo, n0, ldb, kt, tid);
    CP_COMMIT();
}

__global__ void __launch_bounds__(256, 1)
gemm_mma(const __nv_bfloat16* __restrict__ Ahi, const __nv_bfloat16* __restrict__ Alo, int lda,
         const __nv_bfloat16* __restrict__ Bhi, const __nv_bfloat16* __restrict__ Blo, int ldb,
         int ntiles, const float* __restrict__ bias,
         __nv_bfloat16* __restrict__ Chi, __nv_bfloat16* __restrict__ Clo)
{
    extern __shared__ char smem[];
    float* sbias = (float*)(smem + NSTAGE * STAGE_SMEM);
    int tid = threadIdx.x;
    int lane = tid & 31, wid = tid >> 5;
    int wm = wid & 1, wn = wid >> 1;           // 2(m) x 4(n) warp grid, tile 64x64
    int m0 = blockIdx.y * BM, n0 = blockIdx.x * BN;

    if (tid < BN) sbias[tid] = bias[n0 + tid];

    uint32_t sb = smem_to_u32(smem);

    float acc[4][8][4];
    #pragma unroll
    for (int i = 0; i < 4; i++)
        #pragma unroll
        for (int j = 0; j < 8; j++)
            #pragma unroll
            for (int q = 0; q < 4; q++) acc[i][j][q] = 0.f;

    // prologue: stages 0, 1
    cpa_stage(sb + 0 * STAGE_SMEM, Ahi, Alo, m0, lda, Bhi, Blo, n0, ldb, 0, tid);
    if (ntiles > 1)
        cpa_stage(sb + 1 * STAGE_SMEM, Ahi, Alo, m0, lda, Bhi, Blo, n0, ldb, BK, tid);

    int a_row = wm * 64 + (lane & 15);
    int b_row = wn * 64 + (lane & 15);
    int k_half = (lane >> 4) * 8;

    int cur = 0, nxt2 = 2;
    for (int t = 0; t < ntiles; t++) {
        if (t + 1 < ntiles) { CP_WAIT(1); } else { CP_WAIT(0); }
        __syncthreads();
        if (t + 2 < ntiles)
            cpa_stage(sb + nxt2 * STAGE_SMEM, Ahi, Alo, m0, lda, Bhi, Blo, n0, ldb, (t + 2) * BK, tid);

        uint32_t base = sb + cur * STAGE_SMEM;
        uint32_t aHi = base, aLo = base + A_TILE_SMEM;
        uint32_t bHi = base + 2 * A_TILE_SMEM, bLo = bHi + B_TILE_SMEM;

        #pragma unroll
        for (int ko = 0; ko < BK; ko += 16) {
            // B fragments: 8 n8-tiles, hi+lo
            uint32_t bh[8][2], bl[8][2];
            #pragma unroll
            for (int ng = 0; ng < 4; ng++) {
                uint32_t off = (uint32_t)((b_row + ng * 16) * 80 + (ko + k_half) * 2);
                uint32_t r0, r1, r2, r3;
                LDSM4(r0, r1, r2, r3, bHi + off);
                bh[2*ng][0] = r0; bh[2*ng][1] = r2; bh[2*ng+1][0] = r1; bh[2*ng+1][1] = r3;
                LDSM4(r0, r1, r2, r3, bLo + off);
                bl[2*ng][0] = r0; bl[2*ng][1] = r2; bl[2*ng+1][0] = r1; bl[2*ng+1][1] = r3;
            }
            #pragma unroll
            for (int mt = 0; mt < 4; mt++) {
                uint32_t off = (uint32_t)((a_row + mt * 16) * 80 + (ko + k_half) * 2);
                uint32_t ah0, ah1, ah2, ah3, al0, al1, al2, al3;
                LDSM4(ah0, ah1, ah2, ah3, aHi + off);
                LDSM4(al0, al1, al2, al3, aLo + off);
                // term-major: 8 independent MMAs between reuses of each acc
                #pragma unroll
                for (int nt = 0; nt < 8; nt++)
                    MMA16816(acc[mt][nt], ah0, ah1, ah2, ah3, bh[nt][0], bh[nt][1]);
                #pragma unroll
                for (int nt = 0; nt < 8; nt++)
                    MMA16816(acc[mt][nt], ah0, ah1, ah2, ah3, bl[nt][0], bl[nt][1]);
                #pragma unroll
                for (int nt = 0; nt < 8; nt++)
                    MMA16816(acc[mt][nt], al0, al1, al2, al3, bh[nt][0], bh[nt][1]);
            }
        }
        cur = (cur == 2) ? 0 : cur + 1;
        nxt2 = (nxt2 == 2) ? 0 : nxt2 + 1;
    }

    // epilogue: bias + relu + bf16 hi/lo split, packed 32-bit stores
    #pragma unroll
    for (int mt = 0; mt < 4; mt++) {
        int r0g = m0 + wm * 64 + mt * 16 + (lane >> 2);
        #pragma unroll
        for (int nt = 0; nt < 8; nt++) {
            int lc = wn * 64 + nt * 8 + (lane & 3) * 2;
            float b0 = sbias[lc], b1 = sbias[lc + 1];
            #pragma unroll
            for (int half = 0; half < 2; half++) {
                int r = r0g + half * 8;
                float v0 = fmaxf(acc[mt][nt][2*half + 0] + b0, 0.f);
                float v1 = fmaxf(acc[mt][nt][2*half + 1] + b1, 0.f);
                __nv_bfloat16 h0, l0, h1, l1;
                split_bf16(v0, h0, l0);
                split_bf16(v1, h1, l1);
                uint32_t hp = (uint32_t)__bfloat16_as_ushort(h0) | ((uint32_t)__bfloat16_as_ushort(h1) << 16);
                uint32_t lp = (uint32_t)__bfloat16_as_ushort(l0) | ((uint32_t)__bfloat16_as_ushort(l1) << 16);
                *(uint32_t*)(Chi + (size_t)r * H_DIM + n0 + lc) = hp;
                *(uint32_t*)(Clo + (size_t)r * H_DIM + n0 + lc) = lp;
            }
        }
    }
}

// ============================================================================
// Output layer: values[b] = h[b] @ Wout[1024,3] + bout (h reconstructed hi+lo)
// ============================================================================
__global__ void out_kernel(const __nv_bfloat16* __restrict__ hhi,
                           const __nv_bfloat16* __restrict__ hlo,
                           const float* __restrict__ Wout,
                           const float* __restrict__ bout,
                           float* __restrict__ out)
{
    int gt = blockIdx.x * blockDim.x + threadIdx.x;
    int row = gt >> 5;
    int lane = threadIdx.x & 31;
    if (row >= B_ROWS) return;
    const __nv_bfloat16* hr = hhi + (size_t)row * H_DIM;
    const __nv_bfloat16* lr = hlo + (size_t)row * H_DIM;
    float a0 = 0.f, a1 = 0.f, a2 = 0.f;
    for (int d = lane * 2; d < H_DIM; d += 64) {
        uint32_t hp = *(const uint32_t*)(hr + d);
        uint32_t lp = *(const uint32_t*)(lr + d);
        float h0 = __bfloat162float(__ushort_as_bfloat16((unsigned short)(hp & 0xFFFF)))
                 + __bfloat162float(__ushort_as_bfloat16((unsigned short)(lp & 0xFFFF)));
        float h1 = __bfloat162float(__ushort_as_bfloat16((unsigned short)(hp >> 16)))
                 + __bfloat162float(__ushort_as_bfloat16((unsigned short)(lp >> 16)));
        a0 = fmaf(h0, Wout[d*3+0], a0); a0 = fmaf(h1, Wout[(d+1)*3+0], a0);
        a1 = fmaf(h0, Wout[d*3+1], a1); a1 = fmaf(h1, Wout[(d+1)*3+1], a1);
        a2 = fmaf(h0, Wout[d*3+2], a2); a2 = fmaf(h1, Wout[(d+1)*3+2], a2);
    }
    #pragma unroll
    for (int o = 16; o > 0; o >>= 1) {
        a0 += __shfl_down_sync(0xFFFFFFFFu, a0, o);
        a1 += __shfl_down_sync(0xFFFFFFFFu, a1, o);
        a2 += __shfl_down_sync(0xFFFFFFFFu, a2, o);
    }
    if (lane == 0) {
        out[row * 3 + 0] = a0 + bout[0];
        out[row * 3 + 1] = a1 + bout[1];
        out[row * 3 + 2] = a2 + bout[2];
    }
}

// ============================================================================
extern "C" void kernel_launch(void* const* d_in, const int* in_sizes, int n_in,
                              void* d_out, int out_size)
{
    const float* coords     = (const float*)d_in[0];
    const int*   latent_idx = (const int*)  d_in[1];
    const float* latents    = (const float*)d_in[2];
    const float* codebooks  = (const float*)d_in[3];
    const float* mod_W      = (const float*)d_in[4];
    const float* mod_b      = (const float*)d_in[5];
    const float* dec_W0     = (const float*)d_in[6];
    const float* dec_b0     = (const float*)d_in[7];
    const float* dec_Wh     = (const float*)d_in[8];
    const float* dec_bh     = (const float*)d_in[9];
    const float* dec_Wout   = (const float*)d_in[10];
    const float* dec_bout   = (const float*)d_in[11];
    float* out = (float*)d_out;

    cudaFuncSetAttribute(gemm_mma, cudaFuncAttributeMaxDynamicSharedMemorySize, SMEM_GEMM_TOTAL);

    __nv_bfloat16 *pe_hi, *pe_lo, *ha_hi, *ha_lo, *hb_hi, *hb_lo;
    __nv_bfloat16 *w0t_hi, *w0t_lo, *wt_hi, *wt_lo;
    float* bias_p;
    cudaGetSymbolAddress((void**)&pe_hi,  g_pe_hi);
    cudaGetSymbolAddress((void**)&pe_lo,  g_pe_lo);
    cudaGetSymbolAddress((void**)&ha_hi,  g_ha_hi);
    cudaGetSymbolAddress((void**)&ha_lo,  g_ha_lo);
    cudaGetSymbolAddress((void**)&hb_hi,  g_hb_hi);
    cudaGetSymbolAddress((void**)&hb_lo,  g_hb_lo);
    cudaGetSymbolAddress((void**)&w0t_hi, g_w0t_hi);
    cudaGetSymbolAddress((void**)&w0t_lo, g_w0t_lo);
    cudaGetSymbolAddress((void**)&wt_hi,  g_wt_hi);
    cudaGetSymbolAddress((void**)&wt_lo,  g_wt_lo);
    cudaGetSymbolAddress((void**)&bias_p, g_bias);

    setup_kernel<<<1, 1024>>>(latents, latent_idx, codebooks, mod_W, mod_b,
                              dec_b0, dec_bh, out, out_size);
    pe_kernel<<<B_ROWS / 256, 256>>>(coords);

    dim3 grid(H_DIM / BN, B_ROWS / BM);     // (4, 512)
    dim3 tgridH(H_DIM / 32, H_DIM / 32);
    dim3 tgrid0(H_DIM / 32, IN_PAD / 32);
    dim3 tblk(32, 8);

    // layer 0: pe[.,128] @ W0t^T
    wsplit_kernel<<<tgrid0, tblk>>>(dec_W0, IN_DIM, IN_PAD, w0t_hi, w0t_lo);
    gemm_mma<<<grid, 256, SMEM_GEMM_TOTAL>>>(pe_hi, pe_lo, IN_PAD, w0t_hi, w0t_lo, IN_PAD,
                                             IN_PAD / BK, bias_p, ha_hi, ha_lo);
    // hidden layers 1..4 (serial stream => wt buffer reuse is safe)
    wsplit_kernel<<<tgridH, tblk>>>(dec_Wh + (size_t)0 * H_DIM * H_DIM, H_DIM, H_DIM, wt_hi, wt_lo);
    gemm_mma<<<grid, 256, SMEM_GEMM_TOTAL>>>(ha_hi, ha_lo, H_DIM, wt_hi, wt_lo, H_DIM,
                                             H_DIM / BK, bias_p + 1 * H_DIM, hb_hi, hb_lo);
    wsplit_kernel<<<tgridH, tblk>>>(dec_Wh + (size_t)1 * H_DIM * H_DIM, H_DIM, H_DIM, wt_hi, wt_lo);
    gemm_mma<<<grid, 256, SMEM_GEMM_TOTAL>>>(hb_hi, hb_lo, H_DIM, wt_hi, wt_lo, H_DIM,
                                             H_DIM / BK, bias_p + 2 * H_DIM, ha_hi, ha_lo);
    wsplit_kernel<<<tgridH, tblk>>>(dec_Wh + (size_t)2 * H_DIM * H_DIM, H_DIM, H_DIM, wt_hi, wt_lo);
    gemm_mma<<<grid, 256, SMEM_GEMM_TOTAL>>>(ha_hi, ha_lo, H_DIM, wt_hi, wt_lo, H_DIM,
                                             H_DIM / BK, bias_p + 3 * H_DIM, hb_hi, hb_lo);
    wsplit_kernel<<<tgridH, tblk>>>(dec_Wh + (size_t)3 * H_DIM * H_DIM, H_DIM, H_DIM, wt_hi, wt_lo);
    gemm_mma<<<grid, 256, SMEM_GEMM_TOTAL>>>(hb_hi, hb_lo, H_DIM, wt_hi, wt_lo, H_DIM,
                                             H_DIM / BK, bias_p + 4 * H_DIM, ha_hi, ha_lo);

    out_kernel<<<(B_ROWS * 32 + 255) / 256, 256>>>(ha_hi, ha_lo, dec_Wout, dec_bout, out);
}

// round 15
// speedup vs baseline: 1.6576x; 1.6576x over previous
#include <cuda_runtime.h>
#include <cuda_bf16.h>
#include <math.h>
#include <stdint.h>

// ---------------- problem constants ----------------
#define B_ROWS 65536
#define V_DIM  3
#define D_DIM  64
#define K_CB   1024
#define S_ST   4
#define H_DIM  1024
#define L_NUM  5
#define F_NUM  25
#define IN_DIM 102     // C*(2F+1)
#define IN_PAD 128     // padded K for layer 0

// ---------------- GEMM tiling (mma.sync path, base sm_103 ISA) ------------
// CTA 128x128, 8 warps in 2(m) x 4(n), warp tile 64x32. BK=32, 2 smem stages,
// 2 CTAs/SM (launch_bounds minBlocks=2) -> 16 warps/SM, 4 per SMSP.
#define BM 128
#define BN 128
#define BK 32
#define ASTRIDE 40                       // bf16 elems per smem row (80 B, conflict-free ldmatrix)
#define TILE_SMEM (BM * ASTRIDE * 2)     // 10240 B per 128x32 bf16 tile
#define STAGE_SMEM (4 * TILE_SMEM)       // 40960 B: Ahi, Alo, Bhi, Blo
#define NSTAGE 2
#define SMEM_GEMM_TOTAL (NSTAGE * STAGE_SMEM + 512 + 64)   // + bias(128 f32)

// ---------------- persistent scratch (no cudaMalloc allowed) ---------------
__device__ __nv_bfloat16 g_pe_hi[(size_t)B_ROWS * IN_PAD];
__device__ __nv_bfloat16 g_pe_lo[(size_t)B_ROWS * IN_PAD];
__device__ __nv_bfloat16 g_ha_hi[(size_t)B_ROWS * H_DIM];
__device__ __nv_bfloat16 g_ha_lo[(size_t)B_ROWS * H_DIM];
__device__ __nv_bfloat16 g_hb_hi[(size_t)B_ROWS * H_DIM];
__device__ __nv_bfloat16 g_hb_lo[(size_t)B_ROWS * H_DIM];
__device__ __nv_bfloat16 g_w0t_hi[(size_t)H_DIM * IN_PAD];
__device__ __nv_bfloat16 g_w0t_lo[(size_t)H_DIM * IN_PAD];
__device__ __nv_bfloat16 g_wt_hi[(size_t)H_DIM * H_DIM];
__device__ __nv_bfloat16 g_wt_lo[(size_t)H_DIM * H_DIM];
__device__ float g_bias[L_NUM * H_DIM];

// ---------------- PTX helpers (all base-ISA, no 'a' features) --------------
__device__ __forceinline__ uint32_t smem_to_u32(const void* p) {
    uint32_t a;
    asm("{ .reg .u64 t; cvta.to.shared.u64 t, %1; cvt.u32.u64 %0, t; }" : "=r"(a) : "l"(p));
    return a;
}
#define CP_ASYNC16(saddr, gptr) \
    asm volatile("cp.async.cg.shared.global [%0], [%1], 16;" :: "r"(saddr), "l"(gptr))
#define CP_COMMIT() asm volatile("cp.async.commit_group;" ::: "memory")
#define CP_WAIT(n)  asm volatile("cp.async.wait_group %0;" :: "n"(n) : "memory")
#define LDSM4(r0, r1, r2, r3, addr) \
    asm volatile("ldmatrix.sync.aligned.m8n8.x4.shared.b16 {%0,%1,%2,%3}, [%4];" \
        : "=r"(r0), "=r"(r1), "=r"(r2), "=r"(r3) : "r"(addr))
#define MMA16816(d, a0, a1, a2, a3, b0, b1) \
    asm volatile("mma.sync.aligned.m16n8k16.row.col.f32.bf16.bf16.f32 " \
        "{%0,%1,%2,%3}, {%4,%5,%6,%7}, {%8,%9}, {%0,%1,%2,%3};" \
        : "+f"((d)[0]), "+f"((d)[1]), "+f"((d)[2]), "+f"((d)[3]) \
        : "r"(a0), "r"(a1), "r"(a2), "r"(a3), "r"(b0), "r"(b1))

__device__ __forceinline__ void split_bf16(float v, __nv_bfloat16& hi, __nv_bfloat16& lo) {
    hi = __float2bfloat16(v);
    lo = __float2bfloat16(v - __bfloat162float(hi));
}

// ---------------- float-float (df) arithmetic, fast-math-immune ------------
struct df2 { float h, l; };

__device__ __forceinline__ df2 df_norm(float p, float e) {
    float hi = __fadd_rn(p, e);
    float lo = __fsub_rn(e, __fsub_rn(hi, p));
    df2 r; r.h = hi; r.l = lo; return r;
}
__device__ __forceinline__ df2 df_mul(df2 a, df2 b) {
    float p = __fmul_rn(a.h, b.h);
    float e = __fmaf_rn(a.h, b.h, -p);
    e = __fmaf_rn(a.h, b.l, e);
    e = __fmaf_rn(a.l, b.h, e);
    return df_norm(p, e);
}
__device__ __forceinline__ df2 df_one_minus2(df2 t) {
    float b = __fmul_rn(-2.0f, t.h);          // exact
    float s = __fadd_rn(1.0f, b);
    float z = __fsub_rn(s, 1.0f);
    float err = __fadd_rn(__fsub_rn(1.0f, __fsub_rn(s, z)), __fsub_rn(b, z));
    err = __fmaf_rn(-2.0f, t.l, err);
    return df_norm(s, err);
}

// ============================================================================
// Setup kernel: VQ argmin, commit loss, z_q_sum, fused biases (verified R3)
// ============================================================================
__global__ void setup_kernel(const float* __restrict__ latents,
                             const int*   __restrict__ latent_idx,
                             const float* __restrict__ codebooks,
                             const float* __restrict__ mod_W,
                             const float* __restrict__ mod_b,
                             const float* __restrict__ dec_b0,
                             const float* __restrict__ dec_bh,
                             float* __restrict__ out, int out_size)
{
    __shared__ float s_img[S_ST * D_DIM];
    __shared__ float s_zsum[D_DIM];
    __shared__ float s_zz[S_ST];
    __shared__ float s_dist[K_CB];
    __shared__ int   s_didx[K_CB];
    __shared__ int   s_widx[S_ST];
    __shared__ float s_loss[S_ST];
    __shared__ float s_tmp[D_DIM];

    int tid = threadIdx.x;
    const float* img = latents + (size_t)latent_idx[0] * S_ST * D_DIM;
    if (tid < S_ST * D_DIM) s_img[tid] = img[tid];
    __syncthreads();
    if (tid < D_DIM)
        s_zsum[tid] = s_img[tid] + s_img[D_DIM + tid] + s_img[2*D_DIM + tid] + s_img[3*D_DIM + tid];
    if (tid < S_ST) {
        float zz = 0.f;
        for (int d = 0; d < D_DIM; d++) { float v = s_img[tid*D_DIM + d]; zz += v * v; }
        s_zz[tid] = zz;
    }
    __syncthreads();
    for (int s = 0; s < S_ST; s++) {
        const float* z = &s_img[s * D_DIM];
        const float* e = codebooks + ((size_t)s * K_CB + tid) * D_DIM;
        float dot = 0.f, ee = 0.f;
        #pragma unroll 8
        for (int d = 0; d < D_DIM; d++) { float ev = e[d]; dot += z[d] * ev; ee += ev * ev; }
        s_dist[tid] = s_zz[s] - 2.f * dot + ee;
        s_didx[tid] = tid;
        __syncthreads();
        for (int off = K_CB / 2; off > 0; off >>= 1) {
            if (tid < off) {
                float d1 = s_dist[tid], d2 = s_dist[tid + off];
                int i1 = s_didx[tid], i2 = s_didx[tid + off];
                if (d2 < d1 || (d2 == d1 && i2 < i1)) { s_dist[tid] = d2; s_didx[tid] = i2; }
            }
            __syncthreads();
        }
        if (tid == 0) s_widx[s] = s_didx[0];
        __syncthreads();
        if (tid < D_DIM) {
            float diff = codebooks[((size_t)s * K_CB + s_widx[s]) * D_DIM + tid] - z[tid];
            s_tmp[tid] = diff * diff;
        }
        __syncthreads();
        if (tid == 0) {
            float ssum = 0.f;
            for (int d = 0; d < D_DIM; d++) ssum += s_tmp[d];
            s_loss[s] = 0.25f * (ssum / (float)D_DIM);
        }
        __syncthreads();
    }
    {
        int n = tid;
        for (int l = 0; l < L_NUM; l++) {
            float acc = mod_b[l * H_DIM + n];
            const float* Wl = mod_W + (size_t)l * D_DIM * H_DIM + n;
            #pragma unroll 8
            for (int d = 0; d < D_DIM; d++) acc += s_zsum[d] * Wl[(size_t)d * H_DIM];
            acc += (l == 0) ? dec_b0[n] : dec_bh[(l - 1) * H_DIM + n];
            g_bias[l * H_DIM + n] = acc;
        }
    }
    if (tid == 0 && out_size >= B_ROWS * V_DIM + S_ST + 1) {
        float tl = 0.f;
        for (int s = 0; s < S_ST; s++) { out[B_ROWS * V_DIM + s] = (float)s_widx[s]; tl += s_loss[s]; }
        out[B_ROWS * V_DIM + S_ST] = tl;
    }
}

// ============================================================================
// PE kernel: one thread per point; one double sincos seed + df double-angle.
// ============================================================================
__global__ void pe_kernel(const float* __restrict__ coords)
{
    int b = blockIdx.x * blockDim.x + threadIdx.x;
    if (b >= B_ROWS) return;
    float x = coords[b * 2 + 0];
    float y = coords[b * 2 + 1];
    const float PIF = 3.14159265358979323846f;   // fl(pi)

    float a0x = __fmul_rn(x, PIF);
    float a0y = __fmul_rn(y, PIF);
    double sdx, cdx, sdy, cdy;
    sincos((double)a0x, &sdx, &cdx);
    sincos((double)a0y, &sdy, &cdy);

    df2 sx, cx, sy, cy;
    sx.h = (float)sdx; sx.l = (float)(sdx - (double)sx.h);
    cx.h = (float)cdx; cx.l = (float)(cdx - (double)cx.h);
    sy.h = (float)sdy; sy.l = (float)(sdy - (double)sy.h);
    cy.h = (float)cdy; cy.l = (float)(cdy - (double)cy.h);

    size_t base = (size_t)b * IN_PAD;
    uint32_t* rh = (uint32_t*)(g_pe_hi + base);
    uint32_t* rl = (uint32_t*)(g_pe_lo + base);

    {
        __nv_bfloat16 xh, xl, yh, yl;
        split_bf16(x, xh, xl); split_bf16(y, yh, yl);
        rh[0] = (uint32_t)__bfloat16_as_ushort(xh) | ((uint32_t)__bfloat16_as_ushort(yh) << 16);
        rl[0] = (uint32_t)__bfloat16_as_ushort(xl) | ((uint32_t)__bfloat16_as_ushort(yl) << 16);
    }

    #pragma unroll 1
    for (int f = 0; f < F_NUM; f++) {
        float svx = __fadd_rn(sx.h, sx.l), cvx = __fadd_rn(cx.h, cx.l);
        float svy = __fadd_rn(sy.h, sy.l), cvy = __fadd_rn(cy.h, cy.l);
        __nv_bfloat16 h0, l0, h1, l1;
        split_bf16(svx, h0, l0); split_bf16(svy, h1, l1);
        rh[1 + 2*f] = (uint32_t)__bfloat16_as_ushort(h0) | ((uint32_t)__bfloat16_as_ushort(h1) << 16);
        rl[1 + 2*f] = (uint32_t)__bfloat16_as_ushort(l0) | ((uint32_t)__bfloat16_as_ushort(l1) << 16);
        split_bf16(cvx, h0, l0); split_bf16(cvy, h1, l1);
        rh[2 + 2*f] = (uint32_t)__bfloat16_as_ushort(h0) | ((uint32_t)__bfloat16_as_ushort(h1) << 16);
        rl[2 + 2*f] = (uint32_t)__bfloat16_as_ushort(l0) | ((uint32_t)__bfloat16_as_ushort(l1) << 16);
        if (f < F_NUM - 1) {
            df2 s2 = df_mul(sx, cx); s2.h = __fmul_rn(s2.h, 2.f); s2.l = __fmul_rn(s2.l, 2.f);
            df2 ss = df_mul(sx, sx);
            cx = df_one_minus2(ss); sx = s2;
            s2 = df_mul(sy, cy); s2.h = __fmul_rn(s2.h, 2.f); s2.l = __fmul_rn(s2.l, 2.f);
            ss = df_mul(sy, sy);
            cy = df_one_minus2(ss); sy = s2;
        }
    }
    #pragma unroll
    for (int i = 51; i < 64; i++) { rh[i] = 0u; rl[i] = 0u; }
}

// ============================================================================
// Weight transpose + bf16 split:  W[K,1024] fp32  ->  Wt_hi/lo[1024, Kpad] bf16
// ============================================================================
__global__ void wsplit_kernel(const float* __restrict__ W, int Keff, int Kpad,
                              __nv_bfloat16* __restrict__ Th, __nv_bfloat16* __restrict__ Tl)
{
    __shared__ float t[32][33];
    int n0 = blockIdx.x * 32, k0 = blockIdx.y * 32;
    int tx = threadIdx.x, ty = threadIdx.y;    // (32, 8)
    #pragma unroll
    for (int r = 0; r < 4; r++) {
        int k = k0 + ty + r * 8;
        t[ty + r * 8][tx] = (k < Keff) ? W[(size_t)k * H_DIM + n0 + tx] : 0.f;
    }
    __syncthreads();
    #pragma unroll
    for (int r = 0; r < 4; r++) {
        int n = n0 + ty + r * 8;
        int k = k0 + tx;
        float v = t[tx][ty + r * 8];
        __nv_bfloat16 hi, lo; split_bf16(v, hi, lo);
        Th[(size_t)n * Kpad + k] = hi;
        Tl[(size_t)n * Kpad + k] = lo;
    }
}

// ============================================================================
// mma.sync split-bf16 GEMM:  C = relu(A @ Wt^T + bias), emitted as bf16 hi/lo
// CTA 128x128, 8 warps 2x4, warp tile 64x32, BK=32, 2-stage cp.async,
// 2 CTAs per SM (16 warps/SM, 4 per SMSP) for latency hiding.
// ============================================================================
__device__ __forceinline__ void cpa_tile(uint32_t sdst, const __nv_bfloat16* __restrict__ src,
                                         int r0, int ld, int kt, int tid)
{
    #pragma unroll
    for (int it = 0; it < 2; it++) {
        int idx = it * 256 + tid;
        int row = idx >> 2, ch = idx & 3;
        uint32_t s = sdst + (uint32_t)(row * 80 + ch * 16);
        const __nv_bfloat16* g = src + (size_t)(r0 + row) * ld + kt + ch * 8;
        CP_ASYNC16(s, (unsigned long long)__cvta_generic_to_global(g));
    }
}
__device__ __forceinline__ void cpa_stage(uint32_t dst,
        const __nv_bfloat16* Ahi, const __nv_bfloat16* Alo, int m0, int lda,
        const __nv_bfloat16* Bhi, const __nv_bfloat16* Blo, int n0, int ldb,
        int kt, int tid)
{
    cpa_tile(dst + 0 * TILE_SMEM, Ahi, m0, lda, kt, tid);
    cpa_tile(dst + 1 * TILE_SMEM, Alo, m0, lda, kt, tid);
    cpa_tile(dst + 2 * TILE_SMEM, Bhi, n0, ldb, kt, tid);
    cpa_tile(dst + 3 * TILE_SMEM, Blo, n0, ldb, kt, tid);
    CP_COMMIT();
}

__global__ void __launch_bounds__(256, 2)
gemm_mma(const __nv_bfloat16* __restrict__ Ahi, const __nv_bfloat16* __restrict__ Alo, int lda,
         const __nv_bfloat16* __restrict__ Bhi, const __nv_bfloat16* __restrict__ Blo, int ldb,
         int ntiles, const float* __restrict__ bias,
         __nv_bfloat16* __restrict__ Chi, __nv_bfloat16* __restrict__ Clo)
{
    extern __shared__ char smem[];
    float* sbias = (float*)(smem + NSTAGE * STAGE_SMEM);
    int tid = threadIdx.x;
    int lane = tid & 31, wid = tid >> 5;
    int wm = wid & 1, wn = wid >> 1;           // 2(m) x 4(n) warp grid, tile 64x32
    int m0 = blockIdx.y * BM, n0 = blockIdx.x * BN;

    if (tid < BN) sbias[tid] = bias[n0 + tid];

    uint32_t sb = smem_to_u32(smem);

    float acc[4][4][4];
    #pragma unroll
    for (int i = 0; i < 4; i++)
        #pragma unroll
        for (int j = 0; j < 4; j++)
            #pragma unroll
            for (int q = 0; q < 4; q++) acc[i][j][q] = 0.f;

    // prologue: stage 0
    cpa_stage(sb, Ahi, Alo, m0, lda, Bhi, Blo, n0, ldb, 0, tid);

    int a_row = wm * 64 + (lane & 15);
    int b_row = wn * 32 + (lane & 15);
    int k_half = (lane >> 4) * 8;

    int buf = 0;
    for (int t = 0; t < ntiles; t++) {
        if (t + 1 < ntiles) {
            cpa_stage(sb + (buf ^ 1) * STAGE_SMEM, Ahi, Alo, m0, lda, Bhi, Blo, n0, ldb, (t + 1) * BK, tid);
            CP_WAIT(1);
        } else {
            CP_WAIT(0);
        }
        __syncthreads();

        uint32_t base = sb + buf * STAGE_SMEM;
        uint32_t aHi = base, aLo = base + TILE_SMEM;
        uint32_t bHi = base + 2 * TILE_SMEM, bLo = base + 3 * TILE_SMEM;

        #pragma unroll
        for (int ko = 0; ko < BK; ko += 16) {
            uint32_t bh[4][2], bl[4][2];
            #pragma unroll
            for (int ng = 0; ng < 2; ng++) {
                uint32_t off = (uint32_t)((b_row + ng * 16) * 80 + (ko + k_half) * 2);
                uint32_t r0, r1, r2, r3;
                LDSM4(r0, r1, r2, r3, bHi + off);
                bh[2*ng][0] = r0; bh[2*ng][1] = r2; bh[2*ng+1][0] = r1; bh[2*ng+1][1] = r3;
                LDSM4(r0, r1, r2, r3, bLo + off);
                bl[2*ng][0] = r0; bl[2*ng][1] = r2; bl[2*ng+1][0] = r1; bl[2*ng+1][1] = r3;
            }
            #pragma unroll
            for (int mt = 0; mt < 4; mt++) {
                uint32_t off = (uint32_t)((a_row + mt * 16) * 80 + (ko + k_half) * 2);
                uint32_t ah0, ah1, ah2, ah3, al0, al1, al2, al3;
                LDSM4(ah0, ah1, ah2, ah3, aHi + off);
                LDSM4(al0, al1, al2, al3, aLo + off);
                #pragma unroll
                for (int nt = 0; nt < 4; nt++) {
                    MMA16816(acc[mt][nt], ah0, ah1, ah2, ah3, bh[nt][0], bh[nt][1]);
                    MMA16816(acc[mt][nt], ah0, ah1, ah2, ah3, bl[nt][0], bl[nt][1]);
                    MMA16816(acc[mt][nt], al0, al1, al2, al3, bh[nt][0], bh[nt][1]);
                }
            }
        }
        __syncthreads();   // all reads of buf done before next iteration overwrites it
        buf ^= 1;
    }

    // epilogue: bias + relu + bf16 hi/lo split, packed 32-bit stores
    #pragma unroll
    for (int mt = 0; mt < 4; mt++) {
        int r0g = m0 + wm * 64 + mt * 16 + (lane >> 2);
        #pragma unroll
        for (int nt = 0; nt < 4; nt++) {
            int lc = wn * 32 + nt * 8 + (lane & 3) * 2;
            float b0 = sbias[lc], b1 = sbias[lc + 1];
            #pragma unroll
            for (int half = 0; half < 2; half++) {
                int r = r0g + half * 8;
                float v0 = fmaxf(acc[mt][nt][2*half + 0] + b0, 0.f);
                float v1 = fmaxf(acc[mt][nt][2*half + 1] + b1, 0.f);
                __nv_bfloat16 h0, l0, h1, l1;
                split_bf16(v0, h0, l0);
                split_bf16(v1, h1, l1);
                uint32_t hp = (uint32_t)__bfloat16_as_ushort(h0) | ((uint32_t)__bfloat16_as_ushort(h1) << 16);
                uint32_t lp = (uint32_t)__bfloat16_as_ushort(l0) | ((uint32_t)__bfloat16_as_ushort(l1) << 16);
                *(uint32_t*)(Chi + (size_t)r * H_DIM + n0 + lc) = hp;
                *(uint32_t*)(Clo + (size_t)r * H_DIM + n0 + lc) = lp;
            }
        }
    }
}

// ============================================================================
// Output layer: values[b] = h[b] @ Wout[1024,3] + bout (h reconstructed hi+lo)
// ============================================================================
__global__ void out_kernel(const __nv_bfloat16* __restrict__ hhi,
                           const __nv_bfloat16* __restrict__ hlo,
                           const float* __restrict__ Wout,
                           const float* __restrict__ bout,
                           float* __restrict__ out)
{
    int gt = blockIdx.x * blockDim.x + threadIdx.x;
    int row = gt >> 5;
    int lane = threadIdx.x & 31;
    if (row >= B_ROWS) return;
    const __nv_bfloat16* hr = hhi + (size_t)row * H_DIM;
    const __nv_bfloat16* lr = hlo + (size_t)row * H_DIM;
    float a0 = 0.f, a1 = 0.f, a2 = 0.f;
    for (int d = lane * 2; d < H_DIM; d += 64) {
        uint32_t hp = *(const uint32_t*)(hr + d);
        uint32_t lp = *(const uint32_t*)(lr + d);
        float h0 = __bfloat162float(__ushort_as_bfloat16((unsigned short)(hp & 0xFFFF)))
                 + __bfloat162float(__ushort_as_bfloat16((unsigned short)(lp & 0xFFFF)));
        float h1 = __bfloat162float(__ushort_as_bfloat16((unsigned short)(hp >> 16)))
                 + __bfloat162float(__ushort_as_bfloat16((unsigned short)(lp >> 16)));
        a0 = fmaf(h0, Wout[d*3+0], a0); a0 = fmaf(h1, Wout[(d+1)*3+0], a0);
        a1 = fmaf(h0, Wout[d*3+1], a1); a1 = fmaf(h1, Wout[(d+1)*3+1], a1);
        a2 = fmaf(h0, Wout[d*3+2], a2); a2 = fmaf(h1, Wout[(d+1)*3+2], a2);
    }
    #pragma unroll
    for (int o = 16; o > 0; o >>= 1) {
        a0 += __shfl_down_sync(0xFFFFFFFFu, a0, o);
        a1 += __shfl_down_sync(0xFFFFFFFFu, a1, o);
        a2 += __shfl_down_sync(0xFFFFFFFFu, a2, o);
    }
    if (lane == 0) {
        out[row * 3 + 0] = a0 + bout[0];
        out[row * 3 + 1] = a1 + bout[1];
        out[row * 3 + 2] = a2 + bout[2];
    }
}

// ============================================================================
extern "C" void kernel_launch(void* const* d_in, const int* in_sizes, int n_in,
                              void* d_out, int out_size)
{
    const float* coords     = (const float*)d_in[0];
    const int*   latent_idx = (const int*)  d_in[1];
    const float* latents    = (const float*)d_in[2];
    const float* codebooks  = (const float*)d_in[3];
    const float* mod_W      = (const float*)d_in[4];
    const float* mod_b      = (const float*)d_in[5];
    const float* dec_W0     = (const float*)d_in[6];
    const float* dec_b0     = (const float*)d_in[7];
    const float* dec_Wh     = (const float*)d_in[8];
    const float* dec_bh     = (const float*)d_in[9];
    const float* dec_Wout   = (const float*)d_in[10];
    const float* dec_bout   = (const float*)d_in[11];
    float* out = (float*)d_out;

    cudaFuncSetAttribute(gemm_mma, cudaFuncAttributeMaxDynamicSharedMemorySize, SMEM_GEMM_TOTAL);

    __nv_bfloat16 *pe_hi, *pe_lo, *ha_hi, *ha_lo, *hb_hi, *hb_lo;
    __nv_bfloat16 *w0t_hi, *w0t_lo, *wt_hi, *wt_lo;
    float* bias_p;
    cudaGetSymbolAddress((void**)&pe_hi,  g_pe_hi);
    cudaGetSymbolAddress((void**)&pe_lo,  g_pe_lo);
    cudaGetSymbolAddress((void**)&ha_hi,  g_ha_hi);
    cudaGetSymbolAddress((void**)&ha_lo,  g_ha_lo);
    cudaGetSymbolAddress((void**)&hb_hi,  g_hb_hi);
    cudaGetSymbolAddress((void**)&hb_lo,  g_hb_lo);
    cudaGetSymbolAddress((void**)&w0t_hi, g_w0t_hi);
    cudaGetSymbolAddress((void**)&w0t_lo, g_w0t_lo);
    cudaGetSymbolAddress((void**)&wt_hi,  g_wt_hi);
    cudaGetSymbolAddress((void**)&wt_lo,  g_wt_lo);
    cudaGetSymbolAddress((void**)&bias_p, g_bias);

    setup_kernel<<<1, 1024>>>(latents, latent_idx, codebooks, mod_W, mod_b,
                              dec_b0, dec_bh, out, out_size);
    pe_kernel<<<B_ROWS / 256, 256>>>(coords);

    dim3 grid(H_DIM / BN, B_ROWS / BM);     // (8, 512)
    dim3 tgridH(H_DIM / 32, H_DIM / 32);
    dim3 tgrid0(H_DIM / 32, IN_PAD / 32);
    dim3 tblk(32, 8);

    // layer 0: pe[.,128] @ W0t^T
    wsplit_kernel<<<tgrid0, tblk>>>(dec_W0, IN_DIM, IN_PAD, w0t_hi, w0t_lo);
    gemm_mma<<<grid, 256, SMEM_GEMM_TOTAL>>>(pe_hi, pe_lo, IN_PAD, w0t_hi, w0t_lo, IN_PAD,
                                             IN_PAD / BK, bias_p, ha_hi, ha_lo);
    // hidden layers 1..4 (serial stream => wt buffer reuse is safe)
    wsplit_kernel<<<tgridH, tblk>>>(dec_Wh + (size_t)0 * H_DIM * H_DIM, H_DIM, H_DIM, wt_hi, wt_lo);
    gemm_mma<<<grid, 256, SMEM_GEMM_TOTAL>>>(ha_hi, ha_lo, H_DIM, wt_hi, wt_lo, H_DIM,
                                             H_DIM / BK, bias_p + 1 * H_DIM, hb_hi, hb_lo);
    wsplit_kernel<<<tgridH, tblk>>>(dec_Wh + (size_t)1 * H_DIM * H_DIM, H_DIM, H_DIM, wt_hi, wt_lo);
    gemm_mma<<<grid, 256, SMEM_GEMM_TOTAL>>>(hb_hi, hb_lo, H_DIM, wt_hi, wt_lo, H_DIM,
                                             H_DIM / BK, bias_p + 2 * H_DIM, ha_hi, ha_lo);
    wsplit_kernel<<<tgridH, tblk>>>(dec_Wh + (size_t)2 * H_DIM * H_DIM, H_DIM, H_DIM, wt_hi, wt_lo);
    gemm_mma<<<grid, 256, SMEM_GEMM_TOTAL>>>(ha_hi, ha_lo, H_DIM, wt_hi, wt_lo, H_DIM,
                                             H_DIM / BK, bias_p + 3 * H_DIM, hb_hi, hb_lo);
    wsplit_kernel<<<tgridH, tblk>>>(dec_Wh + (size_t)3 * H_DIM * H_DIM, H_DIM, H_DIM, wt_hi, wt_lo);
    gemm_mma<<<grid, 256, SMEM_GEMM_TOTAL>>>(hb_hi, hb_lo, H_DIM, wt_hi, wt_lo, H_DIM,
                                             H_DIM / BK, bias_p + 4 * H_DIM, ha_hi, ha_lo);

    out_kernel<<<(B_ROWS * 32 + 255) / 256, 256>>>(ha_hi, ha_lo, dec_Wout, dec_bout, out);
}